// round 1
// baseline (speedup 1.0000x reference)
#include <cuda_runtime.h>
#include <cstdint>

typedef unsigned long long ull;

#define NPG 9
#define EPG 36
#define NGRAPHS 100000
#define NEDGES (NGRAPHS * EPG)
#define WARPS 12
#define THREADS (WARPS * 32)
#define GB 4   // graphs per warp-batch (amortizes fc1 shared reads)

// ---- packed f32x2 helpers ----
__device__ __forceinline__ ull pack2(float a, float b) {
    ull r; asm("mov.b64 %0, {%1, %2};" : "=l"(r) : "f"(a), "f"(b)); return r;
}
__device__ __forceinline__ void unpack2(ull v, float& a, float& b) {
    asm("mov.b64 {%0, %1}, %2;" : "=f"(a), "=f"(b) : "l"(v));
}
__device__ __forceinline__ ull fma2(ull a, ull b, ull c) {
    ull d; asm("fma.rn.f32x2 %0, %1, %2, %3;" : "=l"(d) : "l"(a), "l"(b), "l"(c)); return d;
}

// per-warp scratch; layout ordered so float4/ulonglong2 accesses stay aligned
struct __align__(16) WS {
    ull   AH1[NPG * 32];     // (A@H1)[n][k] duplicated pairs   2304 B (off 0, 16B)
    ull   comb[GB * 3 * 64]; // st0/st8/ctx dup pairs, GB graphs 6144 B (off 2304)
    float Xs[144];           // X[s][k]                          576 B (off 8448, 16B)
    float AXT[160];          // (A@X)^T [k][n], n=9 zero-pad     640 B (off 9024)
    float H1[288];           // H1[s][k]                        1152 B (off 9664)
    float A[81];             // A[d*9+s]                         324 B
    float deg[9];
    float pad[2];
};

__global__ void __launch_bounds__(THREADS, 1) gqn_kernel(
    const float* __restrict__ x,
    const int*   __restrict__ esrc, const int* __restrict__ edst,
    const float* __restrict__ W1,  const float* __restrict__ b1,
    const float* __restrict__ W2,  const float* __restrict__ b2,
    const float* __restrict__ fc1w, const float* __restrict__ fc1b,
    const float* __restrict__ fc2w, const float* __restrict__ fc2b,
    float* __restrict__ out)
{
    extern __shared__ char smem[];
    float* sFC1 = (float*)smem;                       // 128x64 f32 = 32 KB
    WS* wsAll   = (WS*)(smem + 32768);

    const int tid = threadIdx.x, warp = tid >> 5, lane = tid & 31;

    // fc1 weights into shared (row-major [j][64]); read later as ull pairs
    for (int i = tid; i < 128 * 64; i += THREADS) sFC1[i] = fc1w[i];
    const ull* sFC1u = (const ull*)sFC1;              // [j][32] channel pairs

    // ---- persistent per-lane weight registers ----
    ull W1d[16];                                      // W1[k][c] duplicated
    #pragma unroll
    for (int k = 0; k < 16; k++) { float w = W1[k * 32 + lane]; W1d[k] = pack2(w, w); }
    ull W2p[32];                                      // W2[k][(2c,2c+1)]
    #pragma unroll
    for (int k = 0; k < 32; k++) {
        float2 w = ((const float2*)(W2 + k * 64))[lane];
        W2p[k] = pack2(w.x, w.y);
    }
    const float b1c = b1[lane];
    const ull b1d = pack2(b1c, b1c);
    float2 b2v = ((const float2*)b2)[lane];   const ull b2p   = pack2(b2v.x, b2v.y);
    float2 fbv = ((const float2*)fc1b)[lane]; const ull fc1bp = pack2(fbv.x, fbv.y);
    float2 f2v = ((const float2*)fc2w)[lane];
    const float fc2lo = f2v.x, fc2hi = f2v.y;
    const float fc2bias = fc2b[0];
    const ull ONE2   = pack2(1.f, 1.f);
    const ull NINTH2 = pack2(1.f / 9.f, 1.f / 9.f);
    const ull ZERO2  = pack2(0.f, 0.f);

    WS& ws = wsAll[warp];
    __syncthreads();

    const int gwarp  = blockIdx.x * WARPS + warp;
    const int stride = gridDim.x * WARPS * GB;

    for (int base = gwarp * GB; base < NGRAPHS; base += stride) {
        #pragma unroll 1
        for (int gi = 0; gi < GB; ++gi) {
            const int g = base + gi;

            // ---- S1: load X[9][16] ----
            const float4* xv = (const float4*)(x + (size_t)g * 144);
            ((float4*)ws.Xs)[lane] = xv[lane];
            if (lane < 4) ((float4*)ws.Xs)[32 + lane] = xv[32 + lane];

            // ---- S2: build normalized adjacency A (with self-loops) ----
            ws.A[lane] = 0.f; ws.A[32 + lane] = 0.f;
            if (lane < 17) ws.A[64 + lane] = 0.f;
            if (lane < 9)  ws.deg[lane] = 1.f;          // self-loop
            __syncwarp();
            const int e0 = g * EPG, nb = g * NPG;
            const int s1 = esrc[e0 + lane] - nb, d1 = edst[e0 + lane] - nb;
            int s2 = 0, d2 = 0;
            if (lane < 4) { s2 = esrc[e0 + 32 + lane] - nb; d2 = edst[e0 + 32 + lane] - nb; }
            atomicAdd(&ws.deg[d1], 1.f);
            if (lane < 4) atomicAdd(&ws.deg[d2], 1.f);
            __syncwarp();
            if (lane < 9) ws.deg[lane] = rsqrtf(ws.deg[lane]);   // deg -> dinv
            __syncwarp();
            atomicAdd(&ws.A[d1 * 9 + s1], ws.deg[s1] * ws.deg[d1]);
            if (lane < 4) atomicAdd(&ws.A[d2 * 9 + s2], ws.deg[s2] * ws.deg[d2]);
            if (lane < 9) { float di = ws.deg[lane]; atomicAdd(&ws.A[lane * 10], di * di); }
            __syncwarp();

            // ---- S3: AXT[k][n] = (A@X)[n][k], node 9 zero-padded ----
            #pragma unroll
            for (int it = 0; it < 5; ++it) {
                const int t = lane + 32 * it;
                const int k = t & 15, n = t >> 4;       // t<160 -> n<=9
                float acc = 0.f;
                if (n < 9) {
                    #pragma unroll
                    for (int s = 0; s < 9; s++) acc += ws.A[n * 9 + s] * ws.Xs[s * 16 + k];
                }
                ws.AXT[k * 10 + n] = acc;
            }
            __syncwarp();

            // ---- S4: H1 = relu(AX @ W1 + b1); lane = channel c, f32x2 over node pairs ----
            ull acc4[5];
            #pragma unroll
            for (int np = 0; np < 5; np++) acc4[np] = b1d;
            #pragma unroll
            for (int k = 0; k < 16; k++) {
                #pragma unroll
                for (int np = 0; np < 5; np++) {
                    ull h2 = *(const ull*)&ws.AXT[k * 10 + np * 2];  // (AX[n][k], AX[n+1][k])
                    acc4[np] = fma2(h2, W1d[k], acc4[np]);
                }
            }
            #pragma unroll
            for (int np = 0; np < 5; np++) {
                float lo, hi; unpack2(acc4[np], lo, hi);
                lo = fmaxf(lo, 0.f); hi = fmaxf(hi, 0.f);
                ws.H1[(2 * np) * 32 + lane] = lo;
                if (np < 4) ws.H1[(2 * np + 1) * 32 + lane] = hi;
            }
            __syncwarp();

            // ---- S5: AH1[n][k] = (A@H1)[n][k], stored as duplicated pairs ----
            #pragma unroll
            for (int d = 0; d < 9; ++d) {
                float acc = 0.f;
                #pragma unroll
                for (int s = 0; s < 9; s++) acc += ws.A[d * 9 + s] * ws.H1[s * 32 + lane];
                ws.AH1[d * 32 + lane] = pack2(acc, acc);
            }
            __syncwarp();

            // ---- S6: H2 rows = relu(AH1 @ W2 + b2); keep only ctx-sum + stations ----
            ull ctx = ZERO2, st0 = ZERO2, st8 = ZERO2;
            #pragma unroll
            for (int n = 0; n < 9; n++) {
                ull acc = b2p;
                const ull* row = ws.AH1 + n * 32;
                #pragma unroll
                for (int k = 0; k < 32; k += 2) {
                    ulonglong2 hv = *(const ulonglong2*)(row + k);   // 2 dup values
                    acc = fma2(hv.x, W2p[k],     acc);
                    acc = fma2(hv.y, W2p[k + 1], acc);
                }
                float lo, hi; unpack2(acc, lo, hi);
                lo = fmaxf(lo, 0.f); hi = fmaxf(hi, 0.f);
                ull r = pack2(lo, hi);
                ctx = fma2(r, ONE2, ctx);
                if (n == 0) st0 = r;
                if (n == 8) st8 = r;
            }
            ctx = fma2(ctx, NINTH2, ZERO2);   // mean over 9 nodes

            // stash st0/st8/ctx as dup pairs for the FC stage
            ull* cb = ws.comb + gi * 192;
            {
                float a, b;
                unpack2(st0, a, b); cb[      2 * lane] = pack2(a, a); cb[      2 * lane + 1] = pack2(b, b);
                unpack2(st8, a, b); cb[ 64 + 2 * lane] = pack2(a, a); cb[ 64 + 2 * lane + 1] = pack2(b, b);
                unpack2(ctx, a, b); cb[128 + 2 * lane] = pack2(a, a); cb[128 + 2 * lane + 1] = pack2(b, b);
            }
            __syncwarp();
        }

        // ---- S7: FC head, batched over GB graphs (fc1 pair-load reused GB times) ----
        ull zc[GB];
        #pragma unroll
        for (int gi = 0; gi < GB; gi++) zc[gi] = ZERO2;
        #pragma unroll 4
        for (int j = 0; j < 64; j++) {                 // ctx part: fc1 rows 64..127
            ull w = sFC1u[(64 + j) * 32 + lane];
            #pragma unroll
            for (int gi = 0; gi < GB; gi++)
                zc[gi] = fma2(ws.comb[gi * 192 + 128 + j], w, zc[gi]);
        }
        #pragma unroll
        for (int v = 0; v < 2; ++v) {                  // station 0, station 8
            ull acc[GB];
            #pragma unroll
            for (int gi = 0; gi < GB; gi++) acc[gi] = fc1bp;
            #pragma unroll 4
            for (int j = 0; j < 64; j++) {             // station part: fc1 rows 0..63
                ull w = sFC1u[j * 32 + lane];
                #pragma unroll
                for (int gi = 0; gi < GB; gi++)
                    acc[gi] = fma2(ws.comb[gi * 192 + v * 64 + j], w, acc[gi]);
            }
            #pragma unroll
            for (int gi = 0; gi < GB; gi++) {
                ull z = fma2(zc[gi], ONE2, acc[gi]);   // + shared ctx term
                float lo, hi; unpack2(z, lo, hi);
                lo = fmaxf(lo, 0.f); hi = fmaxf(hi, 0.f);
                float q = fmaf(lo, fc2lo, hi * fc2hi);
                #pragma unroll
                for (int off = 16; off; off >>= 1) q += __shfl_xor_sync(0xffffffff, q, off);
                if (lane == 0) out[(size_t)(base + gi) * 2 + v] = q + fc2bias;
            }
        }
    }
}

extern "C" void kernel_launch(void* const* d_in, const int* in_sizes, int n_in,
                              void* d_out, int out_size) {
    const float* x    = (const float*)d_in[0];
    const int*   ei   = (const int*)  d_in[1];
    // d_in[2] = batch (unused; graph id derivable from node index)
    const float* W1   = (const float*)d_in[3];
    const float* b1   = (const float*)d_in[4];
    const float* W2   = (const float*)d_in[5];
    const float* b2   = (const float*)d_in[6];
    const float* fc1w = (const float*)d_in[7];
    const float* fc1b = (const float*)d_in[8];
    const float* fc2w = (const float*)d_in[9];
    const float* fc2b = (const float*)d_in[10];

    const size_t shmem = 32768 + sizeof(WS) * WARPS;
    cudaFuncSetAttribute(gqn_kernel, cudaFuncAttributeMaxDynamicSharedMemorySize, (int)shmem);
    gqn_kernel<<<152, THREADS, shmem>>>(x, ei, ei + NEDGES,
                                        W1, b1, W2, b2, fc1w, fc1b, fc2w, fc2b,
                                        (float*)d_out);
}

// round 2
// speedup vs baseline: 1.3968x; 1.3968x over previous
#include <cuda_runtime.h>
#include <cstdint>

typedef unsigned long long ull;

#define NPG 9
#define EPG 36
#define NGRAPHS 100000
#define NPAIRS (NGRAPHS / 2)
#define NEDGES (NGRAPHS * EPG)
#define WARPS 12
#define THREADS (WARPS * 32)
#define GB 4                 // graph-PAIRS per warp FC batch (8 graphs)
#define FULLM 0xffffffffu

// ---- packed f32x2 helpers ----
__device__ __forceinline__ ull pack2(float a, float b) {
    ull r; asm("mov.b64 %0, {%1, %2};" : "=l"(r) : "f"(a), "f"(b)); return r;
}
__device__ __forceinline__ void unpack2(ull v, float& a, float& b) {
    asm("mov.b64 {%0, %1}, %2;" : "=f"(a), "=f"(b) : "l"(v));
}
__device__ __forceinline__ ull fma2(ull a, ull b, ull c) {
    ull d; asm("fma.rn.f32x2 %0, %1, %2, %3;" : "=l"(d) : "l"(a), "l"(b), "l"(c)); return d;
}
__device__ __forceinline__ ull add2(ull a, ull b) {
    ull d; asm("add.rn.f32x2 %0, %1, %2;" : "=l"(d) : "l"(a), "l"(b)); return d;
}
__device__ __forceinline__ ull mul2(ull a, ull b) {
    ull d; asm("mul.rn.f32x2 %0, %1, %2;" : "=l"(d) : "l"(a), "l"(b)); return d;
}
__device__ __forceinline__ ull dup2(float a) { return pack2(a, a); }
__device__ __forceinline__ ull relu2(ull v) {
    float a, b; unpack2(v, a, b);
    return pack2(fmaxf(a, 0.f), fmaxf(b, 0.f));
}

// per-warp scratch; all f32x2 values interleaved as (graph0, graph1) pairs
struct __align__(16) WS {
    ull   Xi[144];        // X pair [n][k]                1152 B (off 0)
    ull   Apair[90];      // A pair [n][s], stride 10      720 B (off 1152)
    ull   H1i[288];       // H1 pair [n][c]               2304 B (off 1872)
    ull   comb[GB * 192]; // st0/st8/ctx pairs per batch  6144 B (off 4176)
    float deg[2][12];     // dinv per graph in pair         96 B (off 10320)
};                        // sizeof = 10416 (16B multiple)

__global__ void __launch_bounds__(THREADS, 1) gqn_kernel(
    const float* __restrict__ x,
    const int*   __restrict__ esrc, const int* __restrict__ edst,
    const float* __restrict__ W1,  const float* __restrict__ b1,
    const float* __restrict__ W2,  const float* __restrict__ b2,
    const float* __restrict__ fc1w, const float* __restrict__ fc1b,
    const float* __restrict__ fc2w, const float* __restrict__ fc2b,
    float* __restrict__ out)
{
    extern __shared__ char smem[];
    float* sFC1 = (float*)smem;                 // [128][64] plain, 32 KB
    float* sW2  = (float*)(smem + 32768);       // [32][64]  plain,  8 KB
    WS* wsAll   = (WS*)(smem + 40960);

    const int tid = threadIdx.x, warp = tid >> 5, lane = tid & 31;

    for (int i = tid; i < 128 * 64; i += THREADS) sFC1[i] = fc1w[i];
    for (int i = tid; i < 32 * 64;  i += THREADS) sW2[i]  = W2[i];

    // ---- persistent per-lane weight registers (all graph-invariant -> dup) ----
    ull W1d[16];
    #pragma unroll
    for (int k = 0; k < 16; k++) W1d[k] = dup2(W1[k * 32 + lane]);
    const ull b1d  = dup2(b1[lane]);
    const ull b2dl = dup2(b2[lane]);
    const ull b2dh = dup2(b2[lane + 32]);
    const ull fbl  = dup2(fc1b[lane]);
    const ull fbh  = dup2(fc1b[lane + 32]);
    const ull f2cl = dup2(fc2w[lane]);
    const ull f2ch = dup2(fc2w[lane + 32]);
    const float fc2bias = fc2b[0];
    const ull NINTH2 = dup2(1.f / 9.f);

    WS& ws = wsAll[warp];
    __syncthreads();

    const int gwarp  = blockIdx.x * WARPS + warp;
    const int stride = gridDim.x * WARPS * GB;

    for (int base = gwarp * GB; base < NPAIRS; base += stride) {
        #pragma unroll 1
        for (int pi = 0; pi < GB; ++pi) {
            const int p = base + pi;
            if (p >= NPAIRS) break;

            // ---- S1: load X for both graphs, interleave pairs ----
            const float4* xv = (const float4*)(x + (size_t)p * 288);
            {
                float4 a0 = xv[lane], a1 = xv[36 + lane];
                ulonglong2 u0 = { pack2(a0.x, a1.x), pack2(a0.y, a1.y) };
                ulonglong2 u1 = { pack2(a0.z, a1.z), pack2(a0.w, a1.w) };
                *(ulonglong2*)&ws.Xi[4 * lane]     = u0;
                *(ulonglong2*)&ws.Xi[4 * lane + 2] = u1;
                if (lane < 4) {
                    float4 c0 = xv[32 + lane], c1 = xv[68 + lane];
                    ulonglong2 v0 = { pack2(c0.x, c1.x), pack2(c0.y, c1.y) };
                    ulonglong2 v1 = { pack2(c0.z, c1.z), pack2(c0.w, c1.w) };
                    *(ulonglong2*)&ws.Xi[128 + 4 * lane] = v0;
                    *(ulonglong2*)&ws.Xi[130 + 4 * lane] = v1;
                }
            }

            // ---- S2: build normalized adjacency pairs (match-based, no atomics) ----
            {
                ulonglong2 z2 = make_ulonglong2(0ull, 0ull);
                *(ulonglong2*)&ws.Apair[2 * lane] = z2;
                if (lane < 13) *(ulonglong2*)&ws.Apair[64 + 2 * lane] = z2;
                if (lane < 9) { ws.deg[0][lane] = 1.f; ws.deg[1][lane] = 1.f; }
            }
            __syncwarp();
            #pragma unroll 1
            for (int gg = 0; gg < 2; ++gg) {
                const int g = 2 * p + gg;
                const int* es = esrc + g * EPG;
                const int* ed = edst + g * EPG;
                const int nb = g * NPG;
                const int s1 = es[lane] - nb, d1 = ed[lane] - nb;
                int s2 = 0, d2 = 0;
                if (lane < 4) { s2 = es[32 + lane] - nb; d2 = ed[32 + lane] - nb; }

                unsigned m = __match_any_sync(FULLM, d1);
                if ((int)lane == __ffs(m) - 1) ws.deg[gg][d1] += (float)__popc(m);
                __syncwarp();
                if (lane < 4) {
                    unsigned m2 = __match_any_sync(0xF, d2);
                    if ((int)lane == __ffs(m2) - 1) ws.deg[gg][d2] += (float)__popc(m2);
                }
                __syncwarp();
                if (lane < 9) ws.deg[gg][lane] = rsqrtf(ws.deg[gg][lane]);
                __syncwarp();

                unsigned ma = __match_any_sync(FULLM, (d1 << 4) | s1);
                if ((int)lane == __ffs(ma) - 1) {
                    float* slot = (float*)&ws.Apair[d1 * 10 + s1];
                    slot[gg] += (float)__popc(ma) * ws.deg[gg][s1] * ws.deg[gg][d1];
                }
                __syncwarp();
                if (lane < 4) {
                    unsigned m2 = __match_any_sync(0xF, (d2 << 4) | s2);
                    if ((int)lane == __ffs(m2) - 1) {
                        float* slot = (float*)&ws.Apair[d2 * 10 + s2];
                        slot[gg] += (float)__popc(m2) * ws.deg[gg][s2] * ws.deg[gg][d2];
                    }
                }
                __syncwarp();
                if (lane < 9) {
                    float di = ws.deg[gg][lane];
                    ((float*)&ws.Apair[lane * 10 + lane])[gg] += di * di;
                }
                __syncwarp();
            }

            // ---- S3: Y = X @ W1 (pairs in regs, lane = channel c of 32) ----
            ull y[10];
            y[9] = 0ull;
            #pragma unroll
            for (int n = 0; n < 9; ++n) {
                const ulonglong2* xr = (const ulonglong2*)&ws.Xi[n * 16];
                ull acc = 0ull;
                #pragma unroll
                for (int k2 = 0; k2 < 8; ++k2) {
                    ulonglong2 xp = xr[k2];
                    acc = fma2(xp.x, W1d[2 * k2],     acc);
                    acc = fma2(xp.y, W1d[2 * k2 + 1], acc);
                }
                y[n] = acc;
            }

            // ---- S4: H1 = relu(A@Y + b1)  (elementwise pair mix) ----
            #pragma unroll
            for (int n = 0; n < 9; ++n) {
                const ulonglong2* ar = (const ulonglong2*)&ws.Apair[n * 10];
                ull acc = b1d;
                #pragma unroll
                for (int sp = 0; sp < 5; ++sp) {
                    ulonglong2 av = ar[sp];
                    acc = fma2(av.x, y[2 * sp],     acc);
                    acc = fma2(av.y, y[2 * sp + 1], acc);
                }
                ws.H1i[n * 32 + lane] = relu2(acc);
            }
            __syncwarp();

            // ---- S5: G = H1 @ W2 (lane = channels c, c+32 of 64) ----
            ull gl[10], gh[10];
            #pragma unroll
            for (int n = 0; n < 10; ++n) { gl[n] = 0ull; gh[n] = 0ull; }
            #pragma unroll
            for (int k2 = 0; k2 < 16; ++k2) {
                const int k = 2 * k2;
                const ull w0l = dup2(sW2[k * 64 + lane]);
                const ull w0h = dup2(sW2[k * 64 + 32 + lane]);
                const ull w1l = dup2(sW2[k * 64 + 64 + lane]);
                const ull w1h = dup2(sW2[k * 64 + 96 + lane]);
                #pragma unroll
                for (int n = 0; n < 9; ++n) {
                    ulonglong2 hv = *(const ulonglong2*)&ws.H1i[n * 32 + k];
                    gl[n] = fma2(hv.x, w0l, gl[n]); gh[n] = fma2(hv.x, w0h, gh[n]);
                    gl[n] = fma2(hv.y, w1l, gl[n]); gh[n] = fma2(hv.y, w1h, gh[n]);
                }
            }

            // ---- S6: H2 = relu(A@G + b2); keep ctx mean + stations 0,8 ----
            ull ctxl = 0ull, ctxh = 0ull, st0l = 0ull, st0h = 0ull, st8l = 0ull, st8h = 0ull;
            #pragma unroll
            for (int n = 0; n < 9; ++n) {
                const ulonglong2* ar = (const ulonglong2*)&ws.Apair[n * 10];
                ull al = b2dl, ah = b2dh;
                #pragma unroll
                for (int sp = 0; sp < 5; ++sp) {
                    ulonglong2 av = ar[sp];
                    al = fma2(av.x, gl[2 * sp],     al); ah = fma2(av.x, gh[2 * sp],     ah);
                    al = fma2(av.y, gl[2 * sp + 1], al); ah = fma2(av.y, gh[2 * sp + 1], ah);
                }
                al = relu2(al); ah = relu2(ah);
                ctxl = add2(ctxl, al); ctxh = add2(ctxh, ah);
                if (n == 0) { st0l = al; st0h = ah; }
                if (n == 8) { st8l = al; st8h = ah; }
            }
            ctxl = mul2(ctxl, NINTH2); ctxh = mul2(ctxh, NINTH2);

            ull* cb = &ws.comb[pi * 192];
            cb[lane]       = st0l; cb[32 + lane]  = st0h;
            cb[64 + lane]  = st8l; cb[96 + lane]  = st8h;
            cb[128 + lane] = ctxl; cb[160 + lane] = ctxh;
        }
        __syncwarp();

        // ---- S7: FC head, batched over GB pairs; fc1 loads amortized ----
        ull zc[GB][2], q0a[GB][2], q1a[GB][2];
        #pragma unroll
        for (int pq = 0; pq < GB; ++pq) {
            zc[pq][0] = 0ull; zc[pq][1] = 0ull;
            q0a[pq][0] = fbl; q0a[pq][1] = fbh;
            q1a[pq][0] = fbl; q1a[pq][1] = fbh;
        }
        #pragma unroll 2
        for (int j2 = 0; j2 < 32; ++j2) {
            const int js = 2 * j2;            // station rows js, js+1
            const ull s0l = dup2(sFC1[js * 64 + lane]);
            const ull s0h = dup2(sFC1[js * 64 + 32 + lane]);
            const ull s1l = dup2(sFC1[js * 64 + 64 + lane]);
            const ull s1h = dup2(sFC1[js * 64 + 96 + lane]);
            const int jc = (64 + js) * 64;    // ctx rows 64+js, 65+js
            const ull c0l = dup2(sFC1[jc + lane]);
            const ull c0h = dup2(sFC1[jc + 32 + lane]);
            const ull c1l = dup2(sFC1[jc + 64 + lane]);
            const ull c1h = dup2(sFC1[jc + 96 + lane]);
            #pragma unroll
            for (int pq = 0; pq < GB; ++pq) {
                const ull* cb = &ws.comb[pq * 192];
                ulonglong2 v0 = *(const ulonglong2*)&cb[2 * j2];
                ulonglong2 v1 = *(const ulonglong2*)&cb[64 + 2 * j2];
                ulonglong2 vc = *(const ulonglong2*)&cb[128 + 2 * j2];
                q0a[pq][0] = fma2(v0.x, s0l, q0a[pq][0]); q0a[pq][1] = fma2(v0.x, s0h, q0a[pq][1]);
                q0a[pq][0] = fma2(v0.y, s1l, q0a[pq][0]); q0a[pq][1] = fma2(v0.y, s1h, q0a[pq][1]);
                q1a[pq][0] = fma2(v1.x, s0l, q1a[pq][0]); q1a[pq][1] = fma2(v1.x, s0h, q1a[pq][1]);
                q1a[pq][0] = fma2(v1.y, s1l, q1a[pq][0]); q1a[pq][1] = fma2(v1.y, s1h, q1a[pq][1]);
                zc[pq][0]  = fma2(vc.x, c0l, zc[pq][0]);  zc[pq][1]  = fma2(vc.x, c0h, zc[pq][1]);
                zc[pq][0]  = fma2(vc.y, c1l, zc[pq][0]);  zc[pq][1]  = fma2(vc.y, c1h, zc[pq][1]);
            }
        }

        // ---- epilogue: relu, fc2 dot, warp reduce, store ----
        #pragma unroll
        for (int pq = 0; pq < GB; ++pq) {
            const int P = base + pq;
            #pragma unroll
            for (int v = 0; v < 2; ++v) {
                ull zl = add2(zc[pq][0], v ? q1a[pq][0] : q0a[pq][0]);
                ull zh = add2(zc[pq][1], v ? q1a[pq][1] : q0a[pq][1]);
                zl = relu2(zl); zh = relu2(zh);
                ull qp = fma2(zl, f2cl, 0ull);
                qp = fma2(zh, f2ch, qp);
                float qa, qb; unpack2(qp, qa, qb);
                #pragma unroll
                for (int off = 16; off; off >>= 1) {
                    qa += __shfl_xor_sync(FULLM, qa, off);
                    qb += __shfl_xor_sync(FULLM, qb, off);
                }
                if (lane == 0 && P < NPAIRS) {
                    out[4 * P + v]     = qa + fc2bias;   // graph 2P
                    out[4 * P + 2 + v] = qb + fc2bias;   // graph 2P+1
                }
            }
        }
    }
}

extern "C" void kernel_launch(void* const* d_in, const int* in_sizes, int n_in,
                              void* d_out, int out_size) {
    const float* x    = (const float*)d_in[0];
    const int*   ei   = (const int*)  d_in[1];
    const float* W1   = (const float*)d_in[3];
    const float* b1   = (const float*)d_in[4];
    const float* W2   = (const float*)d_in[5];
    const float* b2   = (const float*)d_in[6];
    const float* fc1w = (const float*)d_in[7];
    const float* fc1b = (const float*)d_in[8];
    const float* fc2w = (const float*)d_in[9];
    const float* fc2b = (const float*)d_in[10];

    const size_t shmem = 40960 + sizeof(WS) * WARPS;
    cudaFuncSetAttribute(gqn_kernel, cudaFuncAttributeMaxDynamicSharedMemorySize, (int)shmem);
    gqn_kernel<<<152, THREADS, shmem>>>(x, ei, ei + NEDGES,
                                        W1, b1, W2, b2, fc1w, fc1b, fc2w, fc2b,
                                        (float*)d_out);
}

// round 3
// speedup vs baseline: 1.4193x; 1.0161x over previous
#include <cuda_runtime.h>
#include <cstdint>

typedef unsigned long long ull;

#define NPG 9
#define EPG 36
#define NGRAPHS 100000
#define NPAIRS (NGRAPHS / 2)
#define NEDGES (NGRAPHS * EPG)
#define WARPS 16
#define THREADS (WARPS * 32)
#define GB 3                 // graph-PAIRS per warp FC batch (6 graphs)
#define FULLM 0xffffffffu

// ---- packed f32x2 helpers ----
__device__ __forceinline__ ull pack2(float a, float b) {
    ull r; asm("mov.b64 %0, {%1, %2};" : "=l"(r) : "f"(a), "f"(b)); return r;
}
__device__ __forceinline__ void unpack2(ull v, float& a, float& b) {
    asm("mov.b64 {%0, %1}, %2;" : "=f"(a), "=f"(b) : "l"(v));
}
__device__ __forceinline__ ull fma2(ull a, ull b, ull c) {
    ull d; asm("fma.rn.f32x2 %0, %1, %2, %3;" : "=l"(d) : "l"(a), "l"(b), "l"(c)); return d;
}
__device__ __forceinline__ ull add2(ull a, ull b) {
    ull d; asm("add.rn.f32x2 %0, %1, %2;" : "=l"(d) : "l"(a), "l"(b)); return d;
}
__device__ __forceinline__ ull mul2(ull a, ull b) {
    ull d; asm("mul.rn.f32x2 %0, %1, %2;" : "=l"(d) : "l"(a), "l"(b)); return d;
}
__device__ __forceinline__ ull dup2(float a) { return pack2(a, a); }
__device__ __forceinline__ ull relu2(ull v) {
    float a, b; unpack2(v, a, b);
    return pack2(fmaxf(a, 0.f), fmaxf(b, 0.f));
}

// shared layout offsets (bytes)
#define OFF_FC1   0        // [128][64] f32   32768 B
#define OFF_W2    32768    // [32][64]  f32    8192 B
#define OFF_W1    40960    // [16][32]  f32    2048 B
#define OFF_B1    43008    // 32 f32            128 B
#define OFF_B2    43136    // 64 f32            256 B
#define OFF_FB    43392    // 64 f32 (fc1b)     256 B
#define OFF_F2    43648    // 64 f32 (fc2w)     256 B
#define OFF_WS    43904

// per-warp scratch; all f32x2 values interleaved as (graph0, graph1) pairs
struct __align__(16) WS {
    ull   Xi[144];        // X pair [n][k]                1152 B
    ull   Apair[90];      // A pair [n][s], stride 10      720 B
    ull   H1i[288];       // H1 pair [n][c]               2304 B
    ull   comb[GB * 192]; // st0/st8/ctx pairs per batch  4608 B
    float deg[2][12];     // dinv per graph in pair         96 B
};                        // 8880 B

__global__ void __launch_bounds__(THREADS, 1) gqn_kernel(
    const float* __restrict__ x,
    const int*   __restrict__ esrc, const int* __restrict__ edst,
    const float* __restrict__ W1,  const float* __restrict__ b1,
    const float* __restrict__ W2,  const float* __restrict__ b2,
    const float* __restrict__ fc1w, const float* __restrict__ fc1b,
    const float* __restrict__ fc2w, const float* __restrict__ fc2b,
    float* __restrict__ out)
{
    extern __shared__ char smem[];
    float* sFC1 = (float*)(smem + OFF_FC1);
    float* sW2  = (float*)(smem + OFF_W2);
    float* sW1  = (float*)(smem + OFF_W1);
    float* cB1  = (float*)(smem + OFF_B1);
    float* cB2  = (float*)(smem + OFF_B2);
    float* cFB  = (float*)(smem + OFF_FB);
    float* cF2  = (float*)(smem + OFF_F2);
    WS* wsAll   = (WS*)(smem + OFF_WS);

    const int tid = threadIdx.x, warp = tid >> 5, lane = tid & 31;

    for (int i = tid; i < 128 * 64; i += THREADS) sFC1[i] = fc1w[i];
    for (int i = tid; i < 32 * 64;  i += THREADS) sW2[i]  = W2[i];
    for (int i = tid; i < 16 * 32;  i += THREADS) sW1[i]  = W1[i];
    if (tid < 32)                    cB1[tid] = b1[tid];
    else if (tid < 96)               cB2[tid - 32] = b2[tid - 32];
    else if (tid < 160)              cFB[tid - 96] = fc1b[tid - 96];
    else if (tid < 224)              cF2[tid - 160] = fc2w[tid - 160];

    const float fc2bias = fc2b[0];

    WS& ws = wsAll[warp];
    __syncthreads();

    const int gwarp  = blockIdx.x * WARPS + warp;
    const int stride = gridDim.x * WARPS * GB;

    for (int base = gwarp * GB; base < NPAIRS; base += stride) {
        #pragma unroll 1
        for (int pi = 0; pi < GB; ++pi) {
            const int p = base + pi;
            if (p >= NPAIRS) break;

            // ---- S1: load X for both graphs, interleave pairs ----
            const float4* xv = (const float4*)(x + (size_t)p * 288);
            {
                float4 a0 = xv[lane], a1 = xv[36 + lane];
                ulonglong2 u0 = { pack2(a0.x, a1.x), pack2(a0.y, a1.y) };
                ulonglong2 u1 = { pack2(a0.z, a1.z), pack2(a0.w, a1.w) };
                *(ulonglong2*)&ws.Xi[4 * lane]     = u0;
                *(ulonglong2*)&ws.Xi[4 * lane + 2] = u1;
                if (lane < 4) {
                    float4 c0 = xv[32 + lane], c1 = xv[68 + lane];
                    ulonglong2 v0 = { pack2(c0.x, c1.x), pack2(c0.y, c1.y) };
                    ulonglong2 v1 = { pack2(c0.z, c1.z), pack2(c0.w, c1.w) };
                    *(ulonglong2*)&ws.Xi[128 + 4 * lane] = v0;
                    *(ulonglong2*)&ws.Xi[130 + 4 * lane] = v1;
                }
            }

            // ---- S2: build normalized adjacency pairs (match-based, no atomics) ----
            {
                ulonglong2 z2 = make_ulonglong2(0ull, 0ull);
                *(ulonglong2*)&ws.Apair[2 * lane] = z2;
                if (lane < 13) *(ulonglong2*)&ws.Apair[64 + 2 * lane] = z2;
                if (lane < 9) { ws.deg[0][lane] = 1.f; ws.deg[1][lane] = 1.f; }
            }
            __syncwarp();
            #pragma unroll 1
            for (int gg = 0; gg < 2; ++gg) {
                const int g = 2 * p + gg;
                const int* es = esrc + g * EPG;
                const int* ed = edst + g * EPG;
                const int nb = g * NPG;
                const int s1 = es[lane] - nb, d1 = ed[lane] - nb;
                int s2 = 0, d2 = 0;
                if (lane < 4) { s2 = es[32 + lane] - nb; d2 = ed[32 + lane] - nb; }

                unsigned m = __match_any_sync(FULLM, d1);
                if ((int)lane == __ffs(m) - 1) ws.deg[gg][d1] += (float)__popc(m);
                __syncwarp();
                if (lane < 4) {
                    unsigned m2 = __match_any_sync(0xF, d2);
                    if ((int)lane == __ffs(m2) - 1) ws.deg[gg][d2] += (float)__popc(m2);
                }
                __syncwarp();
                if (lane < 9) ws.deg[gg][lane] = rsqrtf(ws.deg[gg][lane]);
                __syncwarp();

                unsigned ma = __match_any_sync(FULLM, (d1 << 4) | s1);
                if ((int)lane == __ffs(ma) - 1) {
                    float* slot = (float*)&ws.Apair[d1 * 10 + s1];
                    slot[gg] += (float)__popc(ma) * ws.deg[gg][s1] * ws.deg[gg][d1];
                }
                __syncwarp();
                if (lane < 4) {
                    unsigned m2 = __match_any_sync(0xF, (d2 << 4) | s2);
                    if ((int)lane == __ffs(m2) - 1) {
                        float* slot = (float*)&ws.Apair[d2 * 10 + s2];
                        slot[gg] += (float)__popc(m2) * ws.deg[gg][s2] * ws.deg[gg][d2];
                    }
                }
                __syncwarp();
                if (lane < 9) {
                    float di = ws.deg[gg][lane];
                    ((float*)&ws.Apair[lane * 10 + lane])[gg] += di * di;
                }
                __syncwarp();
            }

            // ---- S3: Y = X @ W1 (k-outer: W1 streamed from shared) ----
            ull y[10];
            #pragma unroll
            for (int n = 0; n < 9; ++n) y[n] = 0ull;
            y[9] = 0ull;
            #pragma unroll
            for (int k2 = 0; k2 < 8; ++k2) {
                const ull w0 = dup2(sW1[(2 * k2) * 32 + lane]);
                const ull w1 = dup2(sW1[(2 * k2 + 1) * 32 + lane]);
                #pragma unroll
                for (int n = 0; n < 9; ++n) {
                    ulonglong2 xp = *(const ulonglong2*)&ws.Xi[n * 16 + 2 * k2];
                    y[n] = fma2(xp.x, w0, y[n]);
                    y[n] = fma2(xp.y, w1, y[n]);
                }
            }

            // ---- S4: H1 = relu(A@Y + b1)  (elementwise pair mix) ----
            {
                const ull b1d = dup2(cB1[lane]);
                #pragma unroll
                for (int n = 0; n < 9; ++n) {
                    const ulonglong2* ar = (const ulonglong2*)&ws.Apair[n * 10];
                    ull acc = b1d;
                    #pragma unroll
                    for (int sp = 0; sp < 5; ++sp) {
                        ulonglong2 av = ar[sp];
                        acc = fma2(av.x, y[2 * sp],     acc);
                        acc = fma2(av.y, y[2 * sp + 1], acc);
                    }
                    ws.H1i[n * 32 + lane] = relu2(acc);
                }
            }
            __syncwarp();

            // ---- S5: G = H1 @ W2 (lane = channels c, c+32 of 64) ----
            ull gl[10], gh[10];
            #pragma unroll
            for (int n = 0; n < 10; ++n) { gl[n] = 0ull; gh[n] = 0ull; }
            #pragma unroll
            for (int k2 = 0; k2 < 16; ++k2) {
                const int k = 2 * k2;
                const ull w0l = dup2(sW2[k * 64 + lane]);
                const ull w0h = dup2(sW2[k * 64 + 32 + lane]);
                const ull w1l = dup2(sW2[k * 64 + 64 + lane]);
                const ull w1h = dup2(sW2[k * 64 + 96 + lane]);
                #pragma unroll
                for (int n = 0; n < 9; ++n) {
                    ulonglong2 hv = *(const ulonglong2*)&ws.H1i[n * 32 + k];
                    gl[n] = fma2(hv.x, w0l, gl[n]); gh[n] = fma2(hv.x, w0h, gh[n]);
                    gl[n] = fma2(hv.y, w1l, gl[n]); gh[n] = fma2(hv.y, w1h, gh[n]);
                }
            }

            // ---- S6: H2 = relu(A@G + b2); keep ctx mean + stations 0,8 ----
            {
                const ull b2dl = dup2(cB2[lane]);
                const ull b2dh = dup2(cB2[lane + 32]);
                ull ctxl = 0ull, ctxh = 0ull, st0l = 0ull, st0h = 0ull, st8l = 0ull, st8h = 0ull;
                #pragma unroll
                for (int n = 0; n < 9; ++n) {
                    const ulonglong2* ar = (const ulonglong2*)&ws.Apair[n * 10];
                    ull al = b2dl, ah = b2dh;
                    #pragma unroll
                    for (int sp = 0; sp < 5; ++sp) {
                        ulonglong2 av = ar[sp];
                        al = fma2(av.x, gl[2 * sp],     al); ah = fma2(av.x, gh[2 * sp],     ah);
                        al = fma2(av.y, gl[2 * sp + 1], al); ah = fma2(av.y, gh[2 * sp + 1], ah);
                    }
                    al = relu2(al); ah = relu2(ah);
                    ctxl = add2(ctxl, al); ctxh = add2(ctxh, ah);
                    if (n == 0) { st0l = al; st0h = ah; }
                    if (n == 8) { st8l = al; st8h = ah; }
                }
                const ull NINTH2 = dup2(1.f / 9.f);
                ctxl = mul2(ctxl, NINTH2); ctxh = mul2(ctxh, NINTH2);

                ull* cb = &ws.comb[pi * 192];
                cb[lane]       = st0l; cb[32 + lane]  = st0h;
                cb[64 + lane]  = st8l; cb[96 + lane]  = st8h;
                cb[128 + lane] = ctxl; cb[160 + lane] = ctxh;
            }
        }
        __syncwarp();

        // ---- S7: FC head, batched over GB pairs; fc1 loads amortized ----
        ull zc[GB][2], q0a[GB][2], q1a[GB][2];
        {
            const ull fbl = dup2(cFB[lane]);
            const ull fbh = dup2(cFB[lane + 32]);
            #pragma unroll
            for (int pq = 0; pq < GB; ++pq) {
                zc[pq][0] = 0ull; zc[pq][1] = 0ull;
                q0a[pq][0] = fbl; q0a[pq][1] = fbh;
                q1a[pq][0] = fbl; q1a[pq][1] = fbh;
            }
        }
        #pragma unroll 2
        for (int j2 = 0; j2 < 32; ++j2) {
            const int js = 2 * j2;            // station rows js, js+1
            const ull s0l = dup2(sFC1[js * 64 + lane]);
            const ull s0h = dup2(sFC1[js * 64 + 32 + lane]);
            const ull s1l = dup2(sFC1[js * 64 + 64 + lane]);
            const ull s1h = dup2(sFC1[js * 64 + 96 + lane]);
            const int jc = (64 + js) * 64;    // ctx rows 64+js, 65+js
            const ull c0l = dup2(sFC1[jc + lane]);
            const ull c0h = dup2(sFC1[jc + 32 + lane]);
            const ull c1l = dup2(sFC1[jc + 64 + lane]);
            const ull c1h = dup2(sFC1[jc + 96 + lane]);
            #pragma unroll
            for (int pq = 0; pq < GB; ++pq) {
                const ull* cb = &ws.comb[pq * 192];
                ulonglong2 v0 = *(const ulonglong2*)&cb[2 * j2];
                ulonglong2 v1 = *(const ulonglong2*)&cb[64 + 2 * j2];
                ulonglong2 vc = *(const ulonglong2*)&cb[128 + 2 * j2];
                q0a[pq][0] = fma2(v0.x, s0l, q0a[pq][0]); q0a[pq][1] = fma2(v0.x, s0h, q0a[pq][1]);
                q0a[pq][0] = fma2(v0.y, s1l, q0a[pq][0]); q0a[pq][1] = fma2(v0.y, s1h, q0a[pq][1]);
                q1a[pq][0] = fma2(v1.x, s0l, q1a[pq][0]); q1a[pq][1] = fma2(v1.x, s0h, q1a[pq][1]);
                q1a[pq][0] = fma2(v1.y, s1l, q1a[pq][0]); q1a[pq][1] = fma2(v1.y, s1h, q1a[pq][1]);
                zc[pq][0]  = fma2(vc.x, c0l, zc[pq][0]);  zc[pq][1]  = fma2(vc.x, c0h, zc[pq][1]);
                zc[pq][0]  = fma2(vc.y, c1l, zc[pq][0]);  zc[pq][1]  = fma2(vc.y, c1h, zc[pq][1]);
            }
        }

        // ---- epilogue: relu, fc2 dot, warp reduce, store ----
        {
            const ull f2cl = dup2(cF2[lane]);
            const ull f2ch = dup2(cF2[lane + 32]);
            #pragma unroll
            for (int pq = 0; pq < GB; ++pq) {
                const int P = base + pq;
                #pragma unroll
                for (int v = 0; v < 2; ++v) {
                    ull zl = add2(zc[pq][0], v ? q1a[pq][0] : q0a[pq][0]);
                    ull zh = add2(zc[pq][1], v ? q1a[pq][1] : q0a[pq][1]);
                    zl = relu2(zl); zh = relu2(zh);
                    ull qp = fma2(zl, f2cl, 0ull);
                    qp = fma2(zh, f2ch, qp);
                    float qa, qb; unpack2(qp, qa, qb);
                    #pragma unroll
                    for (int off = 16; off; off >>= 1) {
                        qa += __shfl_xor_sync(FULLM, qa, off);
                        qb += __shfl_xor_sync(FULLM, qb, off);
                    }
                    if (lane == 0 && P < NPAIRS) {
                        out[4 * P + v]     = qa + fc2bias;   // graph 2P
                        out[4 * P + 2 + v] = qb + fc2bias;   // graph 2P+1
                    }
                }
            }
        }
    }
}

extern "C" void kernel_launch(void* const* d_in, const int* in_sizes, int n_in,
                              void* d_out, int out_size) {
    const float* x    = (const float*)d_in[0];
    const int*   ei   = (const int*)  d_in[1];
    const float* W1   = (const float*)d_in[3];
    const float* b1   = (const float*)d_in[4];
    const float* W2   = (const float*)d_in[5];
    const float* b2   = (const float*)d_in[6];
    const float* fc1w = (const float*)d_in[7];
    const float* fc1b = (const float*)d_in[8];
    const float* fc2w = (const float*)d_in[9];
    const float* fc2b = (const float*)d_in[10];

    const size_t shmem = OFF_WS + sizeof(WS) * WARPS;
    cudaFuncSetAttribute(gqn_kernel, cudaFuncAttributeMaxDynamicSharedMemorySize, (int)shmem);
    gqn_kernel<<<152, THREADS, shmem>>>(x, ei, ei + NEDGES,
                                        W1, b1, W2, b2, fc1w, fc1b, fc2w, fc2b,
                                        (float*)d_out);
}

// round 4
// speedup vs baseline: 1.4857x; 1.0468x over previous
#include <cuda_runtime.h>
#include <cstdint>

typedef unsigned long long ull;

#define NPG 9
#define EPG 36
#define NGRAPHS 100000
#define NPAIRS (NGRAPHS / 2)
#define NEDGES (NGRAPHS * EPG)
#define WARPS 16
#define THREADS (WARPS * 32)
#define GB 3                 // graph-PAIRS per warp FC batch (6 graphs)
#define FULLM 0xffffffffu

// ---- packed f32x2 helpers ----
__device__ __forceinline__ ull pack2(float a, float b) {
    ull r; asm("mov.b64 %0, {%1, %2};" : "=l"(r) : "f"(a), "f"(b)); return r;
}
__device__ __forceinline__ void unpack2(ull v, float& a, float& b) {
    asm("mov.b64 {%0, %1}, %2;" : "=f"(a), "=f"(b) : "l"(v));
}
__device__ __forceinline__ ull fma2(ull a, ull b, ull c) {
    ull d; asm("fma.rn.f32x2 %0, %1, %2, %3;" : "=l"(d) : "l"(a), "l"(b), "l"(c)); return d;
}
__device__ __forceinline__ ull add2(ull a, ull b) {
    ull d; asm("add.rn.f32x2 %0, %1, %2;" : "=l"(d) : "l"(a), "l"(b)); return d;
}
__device__ __forceinline__ ull mul2(ull a, ull b) {
    ull d; asm("mul.rn.f32x2 %0, %1, %2;" : "=l"(d) : "l"(a), "l"(b)); return d;
}
__device__ __forceinline__ ull dup2(float a) { return pack2(a, a); }
__device__ __forceinline__ ull relu2(ull v) {
    float a, b; unpack2(v, a, b);
    return pack2(fmaxf(a, 0.f), fmaxf(b, 0.f));
}

// shared layout offsets (bytes)
#define OFF_FC1   0        // [128][64] f32   32768 B
#define OFF_W2    32768    // [32][64]  f32    8192 B
#define OFF_W1    40960    // [16][32]  f32    2048 B
#define OFF_B1    43008    // 32 f32            128 B
#define OFF_B2    43136    // 64 f32            256 B
#define OFF_FB    43392    // 64 f32 (fc1b)     256 B
#define OFF_F2    43648    // 64 f32 (fc2w)     256 B
#define OFF_WS    43904

// per-warp scratch; all f32x2 values interleaved as (graph0, graph1) pairs
struct __align__(16) WS {
    ull   Xi[144];        // X pair [n][k]                1152 B
    ull   Apair[90];      // A pair [n][s], stride 10      720 B
    ull   H1i[288];       // H1 pair [n][c]               2304 B
    ull   comb[GB * 192]; // st0/st8/ctx pairs per batch  4608 B
};

__global__ void __launch_bounds__(THREADS, 1) gqn_kernel(
    const float* __restrict__ x,
    const int*   __restrict__ esrc, const int* __restrict__ edst,
    const float* __restrict__ W1,  const float* __restrict__ b1,
    const float* __restrict__ W2,  const float* __restrict__ b2,
    const float* __restrict__ fc1w, const float* __restrict__ fc1b,
    const float* __restrict__ fc2w, const float* __restrict__ fc2b,
    float* __restrict__ out)
{
    extern __shared__ char smem[];
    float* sFC1 = (float*)(smem + OFF_FC1);
    float* sW2  = (float*)(smem + OFF_W2);
    float* sW1  = (float*)(smem + OFF_W1);
    float* cB1  = (float*)(smem + OFF_B1);
    float* cB2  = (float*)(smem + OFF_B2);
    float* cFB  = (float*)(smem + OFF_FB);
    float* cF2  = (float*)(smem + OFF_F2);
    WS* wsAll   = (WS*)(smem + OFF_WS);

    const int tid = threadIdx.x, warp = tid >> 5, lane = tid & 31;

    for (int i = tid; i < 128 * 64; i += THREADS) sFC1[i] = fc1w[i];
    for (int i = tid; i < 32 * 64;  i += THREADS) sW2[i]  = W2[i];
    for (int i = tid; i < 16 * 32;  i += THREADS) sW1[i]  = W1[i];
    if (tid < 32)                    cB1[tid] = b1[tid];
    else if (tid < 96)               cB2[tid - 32] = b2[tid - 32];
    else if (tid < 160)              cFB[tid - 96] = fc1b[tid - 96];
    else if (tid < 224)              cF2[tid - 160] = fc2w[tid - 160];

    const float fc2bias = fc2b[0];

    WS& ws = wsAll[warp];
    __syncthreads();

    const int gwarp  = blockIdx.x * WARPS + warp;
    const int stride = gridDim.x * WARPS * GB;

    // ---- prefetch edges for the first pair ----
    int ps0 = 0, ps1 = 0, ps2 = 0, pd0 = 0, pd1 = 0, pd2 = 0;
    {
        int p0 = gwarp * GB; if (p0 >= NPAIRS) p0 = 0;
        const int* eb = esrc + (size_t)p0 * 72;
        const int* db = edst + (size_t)p0 * 72;
        ps0 = eb[lane]; ps1 = eb[32 + lane & 31]; // placeholder fixed below
        ps1 = eb[32 + lane];
        pd0 = db[lane]; pd1 = db[32 + lane];
        if (lane < 8) { ps2 = eb[64 + lane]; pd2 = db[64 + lane]; }
    }

    for (int base = gwarp * GB; base < NPAIRS; base += stride) {
        #pragma unroll 1
        for (int pi = 0; pi < GB; ++pi) {
            const int p = base + pi;
            if (p >= NPAIRS) break;

            // ---- issue X LDGs for this pair (consumed much later) ----
            const float4* xv = (const float4*)(x + (size_t)p * 288);
            float4 xa = xv[lane], xb = xv[36 + lane];
            float4 xc, xd;
            if (lane < 4) { xc = xv[32 + lane]; xd = xv[68 + lane]; }

            // ---- consume prefetched edges; prefetch next pair's edges ----
            const int cs0 = ps0, cs1 = ps1, cs2 = ps2;
            const int cd0 = pd0, cd1 = pd1, cd2 = pd2;
            {
                int np = (pi == GB - 1) ? base + stride : p + 1;
                if (np >= NPAIRS) np = 0;
                const int* eb = esrc + (size_t)np * 72;
                const int* db = edst + (size_t)np * 72;
                ps0 = eb[lane]; ps1 = eb[32 + lane];
                pd0 = db[lane]; pd1 = db[32 + lane];
                if (lane < 8) { ps2 = eb[64 + lane]; pd2 = db[64 + lane]; }
            }

            // ---- zero Apair ----
            {
                ulonglong2 z2 = make_ulonglong2(0ull, 0ull);
                *(ulonglong2*)&ws.Apair[2 * lane] = z2;
                if (lane < 13) *(ulonglong2*)&ws.Apair[64 + 2 * lane] = z2;
            }

            // ---- S2: adjacency via ballots/shuffles, 72 edges in 3 slots ----
            // slot A: edges 0-31 (g0); slot B: 32-63 (lanes<4 g0, else g1); slot C: 64-71 (g1, lanes<8)
            const int b0 = p * 18;              // node base of graph 2p
            const int sA = cs0 - b0,                         dA = cd0 - b0;
            const int obB = (lane < 4) ? 0 : 9;
            const int sB = cs1 - b0 - obB == cs1 - b0 - obB ? cs1 - (b0 + obB) : 0;
            const int dB = cd1 - (b0 + obB);
            const int sC = (lane < 8) ? (cs2 - (b0 + 9)) : 15;
            const int dC = (lane < 8) ? (cd2 - (b0 + 9)) : 15;

            int myDeg = 1;                       // self-loop
            #pragma unroll
            for (int n = 0; n < 9; ++n) {
                unsigned bA = __ballot_sync(FULLM, dA == n);
                unsigned bB = __ballot_sync(FULLM, dB == n);
                unsigned bC = __ballot_sync(FULLM, dC == n);
                int c0 = __popc(bA) + __popc(bB & 0xFu);
                int c1 = __popc(bB & ~0xFu) + __popc(bC);
                if ((int)lane == n)      myDeg += c0;
                if ((int)lane == 16 + n) myDeg += c1;
            }
            const float di  = rsqrtf((float)myDeg);   // lanes 0-8: g0, 16-24: g1
            const float di2 = di * di;

            const float nA = __shfl_sync(FULLM, di, sA) * __shfl_sync(FULLM, di, dA);
            const int ob16 = (lane < 4) ? 0 : 16;
            const float nB = __shfl_sync(FULLM, di, sB + ob16) * __shfl_sync(FULLM, di, dB + ob16);
            const float nC = __shfl_sync(FULLM, di, sC + 16) * __shfl_sync(FULLM, di, dC + 16);

            const unsigned mA = __match_any_sync(FULLM, dA * 16 + sA);
            const unsigned mB = __match_any_sync(FULLM, ob16 * 256 + dB * 16 + sB);
            const unsigned kC = (lane < 8) ? (unsigned)(dC * 16 + sC) : (4096u + lane);
            const unsigned mC = __match_any_sync(FULLM, kC);

            __syncwarp();   // zeros visible
            if ((int)lane == __ffs(mA) - 1) {
                float* sl = (float*)&ws.Apair[dA * 10 + sA];
                sl[0] += (float)__popc(mA) * nA;
            }
            if (lane < 8 && (int)lane == __ffs(mC) - 1) {
                float* sl = (float*)&ws.Apair[dC * 10 + sC];
                sl[1] += (float)__popc(mC) * nC;
            }
            __syncwarp();
            if ((int)lane == __ffs(mB) - 1) {
                float* sl = (float*)&ws.Apair[dB * 10 + sB];
                sl[(lane < 4) ? 0 : 1] += (float)__popc(mB) * nB;
            }
            __syncwarp();
            if (lane < 9)
                ((float*)&ws.Apair[lane * 10 + lane])[0] += di2;
            if (lane >= 16 && lane < 25)
                ((float*)&ws.Apair[(lane - 16) * 10 + (lane - 16)])[1] += di2;

            // ---- S1b: store X pairs (LDG data now long arrived) ----
            {
                ulonglong2 u0 = { pack2(xa.x, xb.x), pack2(xa.y, xb.y) };
                ulonglong2 u1 = { pack2(xa.z, xb.z), pack2(xa.w, xb.w) };
                *(ulonglong2*)&ws.Xi[4 * lane]     = u0;
                *(ulonglong2*)&ws.Xi[4 * lane + 2] = u1;
                if (lane < 4) {
                    ulonglong2 v0 = { pack2(xc.x, xd.x), pack2(xc.y, xd.y) };
                    ulonglong2 v1 = { pack2(xc.z, xd.z), pack2(xc.w, xd.w) };
                    *(ulonglong2*)&ws.Xi[128 + 4 * lane] = v0;
                    *(ulonglong2*)&ws.Xi[130 + 4 * lane] = v1;
                }
            }
            __syncwarp();

            // ---- S3: Y = X @ W1 (k-outer: W1 streamed from shared) ----
            ull y[10];
            #pragma unroll
            for (int n = 0; n < 9; ++n) y[n] = 0ull;
            y[9] = 0ull;
            #pragma unroll
            for (int k2 = 0; k2 < 8; ++k2) {
                const ull w0 = dup2(sW1[(2 * k2) * 32 + lane]);
                const ull w1 = dup2(sW1[(2 * k2 + 1) * 32 + lane]);
                #pragma unroll
                for (int n = 0; n < 9; ++n) {
                    ulonglong2 xp = *(const ulonglong2*)&ws.Xi[n * 16 + 2 * k2];
                    y[n] = fma2(xp.x, w0, y[n]);
                    y[n] = fma2(xp.y, w1, y[n]);
                }
            }

            // ---- S4: H1 = relu(A@Y + b1) ----
            {
                const ull b1d = dup2(cB1[lane]);
                #pragma unroll
                for (int n = 0; n < 9; ++n) {
                    const ulonglong2* ar = (const ulonglong2*)&ws.Apair[n * 10];
                    ull acc = b1d;
                    #pragma unroll
                    for (int sp = 0; sp < 5; ++sp) {
                        ulonglong2 av = ar[sp];
                        acc = fma2(av.x, y[2 * sp],     acc);
                        acc = fma2(av.y, y[2 * sp + 1], acc);
                    }
                    ws.H1i[n * 32 + lane] = relu2(acc);
                }
            }
            __syncwarp();

            // ---- S5: G = H1 @ W2 ----
            ull gl[10], gh[10];
            #pragma unroll
            for (int n = 0; n < 10; ++n) { gl[n] = 0ull; gh[n] = 0ull; }
            #pragma unroll
            for (int k2 = 0; k2 < 16; ++k2) {
                const int k = 2 * k2;
                const ull w0l = dup2(sW2[k * 64 + lane]);
                const ull w0h = dup2(sW2[k * 64 + 32 + lane]);
                const ull w1l = dup2(sW2[k * 64 + 64 + lane]);
                const ull w1h = dup2(sW2[k * 64 + 96 + lane]);
                #pragma unroll
                for (int n = 0; n < 9; ++n) {
                    ulonglong2 hv = *(const ulonglong2*)&ws.H1i[n * 32 + k];
                    gl[n] = fma2(hv.x, w0l, gl[n]); gh[n] = fma2(hv.x, w0h, gh[n]);
                    gl[n] = fma2(hv.y, w1l, gl[n]); gh[n] = fma2(hv.y, w1h, gh[n]);
                }
            }

            // ---- S6: H2 = relu(A@G + b2); ctx mean + stations 0,8 ----
            {
                const ull b2dl = dup2(cB2[lane]);
                const ull b2dh = dup2(cB2[lane + 32]);
                ull ctxl = 0ull, ctxh = 0ull, st0l = 0ull, st0h = 0ull, st8l = 0ull, st8h = 0ull;
                #pragma unroll
                for (int n = 0; n < 9; ++n) {
                    const ulonglong2* ar = (const ulonglong2*)&ws.Apair[n * 10];
                    ull al = b2dl, ah = b2dh;
                    #pragma unroll
                    for (int sp = 0; sp < 5; ++sp) {
                        ulonglong2 av = ar[sp];
                        al = fma2(av.x, gl[2 * sp],     al); ah = fma2(av.x, gh[2 * sp],     ah);
                        al = fma2(av.y, gl[2 * sp + 1], al); ah = fma2(av.y, gh[2 * sp + 1], ah);
                    }
                    al = relu2(al); ah = relu2(ah);
                    ctxl = add2(ctxl, al); ctxh = add2(ctxh, ah);
                    if (n == 0) { st0l = al; st0h = ah; }
                    if (n == 8) { st8l = al; st8h = ah; }
                }
                const ull NINTH2 = dup2(1.f / 9.f);
                ctxl = mul2(ctxl, NINTH2); ctxh = mul2(ctxh, NINTH2);

                ull* cb = &ws.comb[pi * 192];
                cb[lane]       = st0l; cb[32 + lane]  = st0h;
                cb[64 + lane]  = st8l; cb[96 + lane]  = st8h;
                cb[128 + lane] = ctxl; cb[160 + lane] = ctxh;
            }
        }
        __syncwarp();

        // ---- S7: FC head, batched over GB pairs ----
        ull zc[GB][2], q0a[GB][2], q1a[GB][2];
        {
            const ull fbl = dup2(cFB[lane]);
            const ull fbh = dup2(cFB[lane + 32]);
            #pragma unroll
            for (int pq = 0; pq < GB; ++pq) {
                zc[pq][0] = 0ull; zc[pq][1] = 0ull;
                q0a[pq][0] = fbl; q0a[pq][1] = fbh;
                q1a[pq][0] = fbl; q1a[pq][1] = fbh;
            }
        }
        #pragma unroll 2
        for (int j2 = 0; j2 < 32; ++j2) {
            const int js = 2 * j2;
            const ull s0l = dup2(sFC1[js * 64 + lane]);
            const ull s0h = dup2(sFC1[js * 64 + 32 + lane]);
            const ull s1l = dup2(sFC1[js * 64 + 64 + lane]);
            const ull s1h = dup2(sFC1[js * 64 + 96 + lane]);
            const int jc = (64 + js) * 64;
            const ull c0l = dup2(sFC1[jc + lane]);
            const ull c0h = dup2(sFC1[jc + 32 + lane]);
            const ull c1l = dup2(sFC1[jc + 64 + lane]);
            const ull c1h = dup2(sFC1[jc + 96 + lane]);
            #pragma unroll
            for (int pq = 0; pq < GB; ++pq) {
                const ull* cb = &ws.comb[pq * 192];
                ulonglong2 v0 = *(const ulonglong2*)&cb[2 * j2];
                ulonglong2 v1 = *(const ulonglong2*)&cb[64 + 2 * j2];
                ulonglong2 vc = *(const ulonglong2*)&cb[128 + 2 * j2];
                q0a[pq][0] = fma2(v0.x, s0l, q0a[pq][0]); q0a[pq][1] = fma2(v0.x, s0h, q0a[pq][1]);
                q0a[pq][0] = fma2(v0.y, s1l, q0a[pq][0]); q0a[pq][1] = fma2(v0.y, s1h, q0a[pq][1]);
                q1a[pq][0] = fma2(v1.x, s0l, q1a[pq][0]); q1a[pq][1] = fma2(v1.x, s0h, q1a[pq][1]);
                q1a[pq][0] = fma2(v1.y, s1l, q1a[pq][0]); q1a[pq][1] = fma2(v1.y, s1h, q1a[pq][1]);
                zc[pq][0]  = fma2(vc.x, c0l, zc[pq][0]);  zc[pq][1]  = fma2(vc.x, c0h, zc[pq][1]);
                zc[pq][0]  = fma2(vc.y, c1l, zc[pq][0]);  zc[pq][1]  = fma2(vc.y, c1h, zc[pq][1]);
            }
        }

        // ---- epilogue ----
        {
            const ull f2cl = dup2(cF2[lane]);
            const ull f2ch = dup2(cF2[lane + 32]);
            #pragma unroll
            for (int pq = 0; pq < GB; ++pq) {
                const int P = base + pq;
                #pragma unroll
                for (int v = 0; v < 2; ++v) {
                    ull zl = add2(zc[pq][0], v ? q1a[pq][0] : q0a[pq][0]);
                    ull zh = add2(zc[pq][1], v ? q1a[pq][1] : q0a[pq][1]);
                    zl = relu2(zl); zh = relu2(zh);
                    ull qp = fma2(zl, f2cl, 0ull);
                    qp = fma2(zh, f2ch, qp);
                    float qa, qb; unpack2(qp, qa, qb);
                    #pragma unroll
                    for (int off = 16; off; off >>= 1) {
                        qa += __shfl_xor_sync(FULLM, qa, off);
                        qb += __shfl_xor_sync(FULLM, qb, off);
                    }
                    if (lane == 0 && P < NPAIRS) {
                        out[4 * P + v]     = qa + fc2bias;
                        out[4 * P + 2 + v] = qb + fc2bias;
                    }
                }
            }
        }
    }
}

extern "C" void kernel_launch(void* const* d_in, const int* in_sizes, int n_in,
                              void* d_out, int out_size) {
    const float* x    = (const float*)d_in[0];
    const int*   ei   = (const int*)  d_in[1];
    const float* W1   = (const float*)d_in[3];
    const float* b1   = (const float*)d_in[4];
    const float* W2   = (const float*)d_in[5];
    const float* b2   = (const float*)d_in[6];
    const float* fc1w = (const float*)d_in[7];
    const float* fc1b = (const float*)d_in[8];
    const float* fc2w = (const float*)d_in[9];
    const float* fc2b = (const float*)d_in[10];

    const size_t shmem = OFF_WS + sizeof(WS) * WARPS;
    cudaFuncSetAttribute(gqn_kernel, cudaFuncAttributeMaxDynamicSharedMemorySize, (int)shmem);
    gqn_kernel<<<152, THREADS, shmem>>>(x, ei, ei + NEDGES,
                                        W1, b1, W2, b2, fc1w, fc1b, fc2w, fc2b,
                                        (float*)d_out);
}